// round 12
// baseline (speedup 1.0000x reference)
#include <cuda_runtime.h>
#include <cuda_bf16.h>
#include <math.h>

#define DIMC   256
#define NPIX   4096
#define HEADS  4
#define KD     32
#define HD     64
#define BATCH  2
#define HIDDEN 512
#define EPS    1e-5f
#define ATT_SCALE 0.17677669529663687f   // 32^-0.5

typedef unsigned long long u64;
typedef unsigned int u32;
union F2 { u64 u; float2 f; };

__device__ __forceinline__ u64 ffma2(u64 a, u64 b, u64 c) {
    u64 d; asm("fma.rn.f32x2 %0, %1, %2, %3;" : "=l"(d) : "l"(a), "l"(b), "l"(c)); return d;
}
__device__ __forceinline__ u64 bcast2(float x) { F2 t; t.f.x = x; t.f.y = x; return t.u; }

// ---------------- scratch (device globals; no allocation allowed) ------------
__device__ __nv_bfloat16 g_Qh[BATCH*HEADS*NPIX*KD];  // [b][h][n][k], scaled, hi
__device__ __nv_bfloat16 g_Ql[BATCH*HEADS*NPIX*KD];  //                        lo
__device__ __nv_bfloat16 g_Kh[BATCH*HEADS*NPIX*KD];
__device__ __nv_bfloat16 g_Kl[BATCH*HEADS*NPIX*KD];
__device__ float g_V [BATCH*DIMC*NPIX];              // [b][h*64+d][n]  fp32 (pe)
__device__ __nv_bfloat16 g_Vh[BATCH*DIMC*NPIX];      // split-bf16 V (attn)
__device__ __nv_bfloat16 g_Vl[BATCH*DIMC*NPIX];
__device__ float g_Y[BATCH*DIMC*NPIX];               // attn out + pe

// ---------------- helpers ----------------------------------------------------
__device__ __forceinline__ u32 smem_u32(const void* p) {
    u32 a; asm("{ .reg .u64 t; cvta.to.shared.u64 t, %1; cvt.u32.u64 %0, t; }" : "=r"(a) : "l"(p));
    return a;
}
__device__ __forceinline__ u32 packbf(float lo, float hi) {
    u32 r; asm("cvt.rn.bf16x2.f32 %0, %1, %2;" : "=r"(r) : "f"(hi), "f"(lo)); return r;
}
__device__ __forceinline__ float bhi(float x) {
    return __bfloat162float(__float2bfloat16_rn(x));
}
__device__ __forceinline__ void bsplit(float x, unsigned short &h, unsigned short &l) {
    __nv_bfloat16 hh = __float2bfloat16_rn(x);
    __nv_bfloat16 ll = __float2bfloat16_rn(x - __bfloat162float(hh));
    h = __bfloat16_as_ushort(hh); l = __bfloat16_as_ushort(ll);
}
__device__ __forceinline__ void cpa16(u32 dst, const void* src) {
    asm volatile("cp.async.cg.shared.global [%0], [%1], 16;" :: "r"(dst), "l"(src));
}

#define LDSM_X4(r0,r1,r2,r3,a) \
    asm volatile("ldmatrix.sync.aligned.m8n8.x4.shared.b16 {%0,%1,%2,%3}, [%4];" \
        : "=r"(r0),"=r"(r1),"=r"(r2),"=r"(r3) : "r"(a))

__device__ __forceinline__ void mma16816(float* d, const u32* a, u32 b0, u32 b1) {
    asm volatile("mma.sync.aligned.m16n8k16.row.col.f32.bf16.bf16.f32 "
        "{%0,%1,%2,%3}, {%4,%5,%6,%7}, {%8,%9}, {%0,%1,%2,%3};"
        : "+f"(d[0]), "+f"(d[1]), "+f"(d[2]), "+f"(d[3])
        : "r"(a[0]), "r"(a[1]), "r"(a[2]), "r"(a[3]), "r"(b0), "r"(b1));
}

// =============================================================================
// Kernel 1: qkv = BN(W @ x); Q,K -> split-bf16 [n][k]; V -> fp32 + split-bf16.
// =============================================================================
#define WS 68
#define XS 68
__global__ __launch_bounds__(256) void qkv_kernel(
    const float* __restrict__ x, const float* __restrict__ w,
    const float* __restrict__ gg, const float* __restrict__ bb,
    const float* __restrict__ mm, const float* __restrict__ vv)
{
    __shared__ float Wt[16*WS];
    __shared__ float Xt[16*XS];
    const int tid = threadIdx.x;
    const int n0 = blockIdx.x * 64;
    const int c0 = blockIdx.y * 64;
    const int b  = blockIdx.z;
    const int tc = tid & 15, tn = tid >> 4;
    const int wrow = tid >> 2, wseg = tid & 3;
    const int xkk  = tid >> 4, xseg = tid & 15;

    const float* xb = x + (size_t)b * DIMC * NPIX;

    F2 acc[4][2];
#pragma unroll
    for (int i = 0; i < 4; i++) { acc[i][0].u = 0ull; acc[i][1].u = 0ull; }

    for (int k0 = 0; k0 < DIMC; k0 += 16) {
        float4 w4 = *(const float4*)&w[(c0 + wrow) * DIMC + k0 + wseg * 4];
        float4 x4 = *(const float4*)&xb[(size_t)(k0 + xkk) * NPIX + n0 + xseg * 4];
        __syncthreads();
        Wt[(wseg*4+0)*WS + wrow] = w4.x;
        Wt[(wseg*4+1)*WS + wrow] = w4.y;
        Wt[(wseg*4+2)*WS + wrow] = w4.z;
        Wt[(wseg*4+3)*WS + wrow] = w4.w;
        *(float4*)&Xt[xkk*XS + xseg*4] = x4;
        __syncthreads();
#pragma unroll
        for (int kk = 0; kk < 16; kk++) {
            float4 a4 = *(const float4*)&Wt[kk*WS + tc*4];
            ulonglong2 bp = *(const ulonglong2*)&Xt[kk*XS + tn*4];
            float av[4] = {a4.x, a4.y, a4.z, a4.w};
#pragma unroll
            for (int i = 0; i < 4; i++) {
                u64 a2 = bcast2(av[i]);
                acc[i][0].u = ffma2(a2, bp.x, acc[i][0].u);
                acc[i][1].u = ffma2(a2, bp.y, acc[i][1].u);
            }
        }
    }

#pragma unroll
    for (int ii = 0; ii < 4; ii++) {
        int c = c0 + tc * 4 + ii;
        float s    = gg[c] * rsqrtf(vv[c] + EPS);
        float beta = bb[c] - mm[c] * s;
        float vals[4];
        vals[0] = fmaf(acc[ii][0].f.x, s, beta);
        vals[1] = fmaf(acc[ii][0].f.y, s, beta);
        vals[2] = fmaf(acc[ii][1].f.x, s, beta);
        vals[3] = fmaf(acc[ii][1].f.y, s, beta);
        int h = c >> 7, off = c & 127;
        if (off < 64) {
            bool isq = off < 32;
            int k = off & 31;
            float sc = isq ? ATT_SCALE : 1.0f;
            unsigned short* Hd = (unsigned short*)(isq ? g_Qh : g_Kh);
            unsigned short* Ld = (unsigned short*)(isq ? g_Ql : g_Kl);
            size_t base = ((size_t)(b*HEADS + h) * NPIX + n0 + tn*4) * KD + k;
#pragma unroll
            for (int j = 0; j < 4; j++) {
                unsigned short hh, ll;
                bsplit(vals[j] * sc, hh, ll);
                Hd[base + (size_t)j*KD] = hh;
                Ld[base + (size_t)j*KD] = ll;
            }
        } else {
            size_t row = (size_t)(b*DIMC + h*HD + (off-64)) * NPIX + n0 + tn*4;
            *(float4*)&g_V[row] = make_float4(vals[0], vals[1], vals[2], vals[3]);
            float h0 = bhi(vals[0]), h1 = bhi(vals[1]);
            float h2 = bhi(vals[2]), h3 = bhi(vals[3]);
            *(uint2*)&g_Vh[row] = make_uint2(packbf(h0, h1), packbf(h2, h3));
            *(uint2*)&g_Vl[row] = make_uint2(packbf(vals[0]-h0, vals[1]-h1),
                                             packbf(vals[2]-h2, vals[3]-h3));
        }
    }
}

// =============================================================================
// Kernel 2: flash attention via mma.sync, split-bf16 3-pass.
//   cp.async double-buffered K/V tiles, ldmatrix.x4 fragments.
//   8 warps x 16 query rows; 32 j-tiles of 128 processed as 2 halves of 64.
// smem:
//   Qh/Ql [128][32] bf16 stride 80B       : 2 x 10240
//   stage s in {0,1}: Kh,Kl [128][32]@80B (2 x 10240) + Vh,Vl [64][128]@272B (2 x 17408)
// =============================================================================
#define AQH_O 0
#define AQL_O 10240
#define STG_O 20480
#define SKH 0
#define SKL 10240
#define SVH 20480
#define SVL 37888
#define STG_SZ 55296
#define ATT_SMEM_BYTES (STG_O + 2*STG_SZ)   // 131072
#define NJ 32

__global__ __launch_bounds__(256) void attn_kernel()
{
    extern __shared__ char smb[];
    const int tid  = threadIdx.x;
    const int wid  = tid >> 5;
    const int lane = tid & 31;
    const int ib = blockIdx.x, h = blockIdx.y, b = blockIdx.z;
    const int i0 = ib * 128;
    const size_t bh = (size_t)(b*HEADS + h);

    const __nv_bfloat16* Qhg = g_Qh + bh * NPIX * KD;
    const __nv_bfloat16* Qlg = g_Ql + bh * NPIX * KD;
    const __nv_bfloat16* Khg = g_Kh + bh * NPIX * KD;
    const __nv_bfloat16* Klg = g_Kl + bh * NPIX * KD;
    const __nv_bfloat16* Vhg = g_Vh + (size_t)(b*DIMC + h*HD) * NPIX;
    const __nv_bfloat16* Vlg = g_Vl + (size_t)(b*DIMC + h*HD) * NPIX;
    float* Yg = g_Y + (size_t)(b*DIMC + h*HD) * NPIX;

    const u32 sbase = smem_u32(smb);

    // ---- load Q tile once: 128 rows x 32 bf16 ----
#pragma unroll
    for (int t = tid; t < 512; t += 256) {
        int row = t >> 2, ch = t & 3;
        cpa16(sbase + AQH_O + row*80 + ch*16, Qhg + (size_t)(i0+row)*KD + ch*8);
        cpa16(sbase + AQL_O + row*80 + ch*16, Qlg + (size_t)(i0+row)*KD + ch*8);
    }
    asm volatile("cp.async.commit_group;" ::: "memory");

    // ---- prefetch stage 0 (jt = 0) ----
    {
        const u32 st = sbase + STG_O;
#pragma unroll
        for (int t = tid; t < 512; t += 256) {
            int row = t >> 2, ch = t & 3;
            cpa16(st + SKH + row*80 + ch*16, Khg + (size_t)row*KD + ch*8);
            cpa16(st + SKL + row*80 + ch*16, Klg + (size_t)row*KD + ch*8);
        }
#pragma unroll
        for (int t = tid; t < 1024; t += 256) {
            int row = t >> 4, ch = t & 15;
            cpa16(st + SVH + row*272 + ch*16, Vhg + (size_t)row*NPIX + ch*8);
            cpa16(st + SVL + row*272 + ch*16, Vlg + (size_t)row*NPIX + ch*8);
        }
        asm volatile("cp.async.commit_group;" ::: "memory");
    }

    // ---- Q A-fragments (wait for Q group: 1 group may remain pending) ----
    asm volatile("cp.async.wait_group 1;" ::: "memory");
    __syncthreads();
    const int i0w = wid * 16;
    const int qrow = i0w + (lane & 7) + ((lane >> 3) & 1) * 8;
    const u32 qcb  = ((lane >> 4) & 1) * 16;
    u32 qh[2][4], ql[2][4];
#pragma unroll
    for (int ks = 0; ks < 2; ks++) {
        LDSM_X4(qh[ks][0], qh[ks][1], qh[ks][2], qh[ks][3],
                sbase + AQH_O + qrow*80 + ks*32 + qcb);
        LDSM_X4(ql[ks][0], ql[ks][1], ql[ks][2], ql[ks][3],
                sbase + AQL_O + qrow*80 + ks*32 + qcb);
    }

    // fragment lane addressing
    const u32 kfr = (lane & 7)*80 + (lane >> 3)*16;     // K: 4 mats = ks0.b0,ks0.b1,ks1.b0,ks1.b1
    const u32 vfr = (lane & 7)*272 + (lane >> 3)*16;    // V: 4 mats = kc.b0,kc.b1,kc+1.b0,kc+1.b1

    float o[8][4];
#pragma unroll
    for (int nd = 0; nd < 8; nd++)
#pragma unroll
        for (int e = 0; e < 4; e++) o[nd][e] = 0.f;
    float ls0 = 0.f, ls1 = 0.f;

    for (int jt = 0; jt < NJ; jt++) {
        asm volatile("cp.async.wait_group 0;" ::: "memory");
        __syncthreads();

        // prefetch jt+1 into the other stage (safe: all threads past compute(jt-1))
        if (jt + 1 < NJ) {
            const u32 st = sbase + STG_O + ((jt+1) & 1)*STG_SZ;
            const int j0n = (jt+1) * 128;
#pragma unroll
            for (int t = tid; t < 512; t += 256) {
                int row = t >> 2, ch = t & 3;
                cpa16(st + SKH + row*80 + ch*16, Khg + (size_t)(j0n+row)*KD + ch*8);
                cpa16(st + SKL + row*80 + ch*16, Klg + (size_t)(j0n+row)*KD + ch*8);
            }
#pragma unroll
            for (int t = tid; t < 1024; t += 256) {
                int row = t >> 4, ch = t & 15;
                cpa16(st + SVH + row*272 + ch*16, Vhg + (size_t)row*NPIX + j0n + ch*8);
                cpa16(st + SVL + row*272 + ch*16, Vlg + (size_t)row*NPIX + j0n + ch*8);
            }
        }
        asm volatile("cp.async.commit_group;" ::: "memory");

        const u32 st = sbase + STG_O + (jt & 1)*STG_SZ;

#pragma unroll
        for (int half = 0; half < 2; half++) {
            // ---- S = Q^T K over 64 j: 8 D-frags, 3-pass split ----
            float sd[8][4];
#pragma unroll
            for (int jn = 0; jn < 8; jn++)
#pragma unroll
                for (int e = 0; e < 4; e++) sd[jn][e] = 0.f;

            const u32 kh_b = st + SKH + half*5120 + kfr;
            const u32 kl_b = st + SKL + half*5120 + kfr;
#pragma unroll
            for (int jn = 0; jn < 8; jn++) {
                u32 k0,k1,k2,k3, l0,l1,l2,l3;
                LDSM_X4(k0,k1,k2,k3, kh_b + jn*640);
                LDSM_X4(l0,l1,l2,l3, kl_b + jn*640);
                mma16816(sd[jn], qh[0], k0, k1);
                mma16816(sd[jn], qh[1], k2, k3);
                mma16816(sd[jn], qh[0], l0, l1);
                mma16816(sd[jn], qh[1], l2, l3);
                mma16816(sd[jn], ql[0], k0, k1);
                mma16816(sd[jn], ql[1], k2, k3);
            }

            // ---- exp + row sums + P A-frags (hi/lo) ----
            u32 ph[4][4], pl[4][4];
#pragma unroll
            for (int jn = 0; jn < 8; jn++) {
                float p0 = __expf(sd[jn][0]);
                float p1 = __expf(sd[jn][1]);
                float p2 = __expf(sd[jn][2]);
                float p3 = __expf(sd[jn][3]);
                ls0 += p0 + p1;
                ls1 += p2 + p3;
                float h0 = bhi(p0), h1 = bhi(p1), h2 = bhi(p2), h3 = bhi(p3);
                int af = jn >> 1, sel = (jn & 1) * 2;
                ph[af][sel+0] = packbf(h0, h1);
                ph[af][sel+1] = packbf(h2, h3);
                pl[af][sel+0] = packbf(p0 - h0, p1 - h1);
                pl[af][sel+1] = packbf(p2 - h2, p3 - h3);
            }

            // ---- O += P V^T over this half ----
            const u32 vh_b = st + SVH + half*128 + vfr;
            const u32 vl_b = st + SVL + half*128 + vfr;
#pragma unroll
            for (int p = 0; p < 2; p++) {
#pragma unroll
                for (int nd = 0; nd < 8; nd++) {
                    u32 a0,a1,a2,a3, c0,c1,c2,c3;
                    LDSM_X4(a0,a1,a2,a3, vh_b + nd*2176 + p*64);
                    LDSM_X4(c0,c1,c2,c3, vl_b + nd*2176 + p*64);
                    mma16816(o[nd], ph[2*p],   a0, a1);
                    mma16816(o[nd], ph[2*p+1], a2, a3);
                    mma16816(o[nd], ph[2*p],   c0, c1);
                    mma16816(o[nd], ph[2*p+1], c2, c3);
                    mma16816(o[nd], pl[2*p],   a0, a1);
                    mma16816(o[nd], pl[2*p+1], a2, a3);
                }
            }
        }
    }

    // ---- row sums across the 4 lanes sharing each row ----
    ls0 += __shfl_xor_sync(0xFFFFFFFF, ls0, 1);
    ls0 += __shfl_xor_sync(0xFFFFFFFF, ls0, 2);
    ls1 += __shfl_xor_sync(0xFFFFFFFF, ls1, 1);
    ls1 += __shfl_xor_sync(0xFFFFFFFF, ls1, 2);
    float inv0 = 1.0f / ls0;
    float inv1 = 1.0f / ls1;

    // ---- store O ----
    const int iA = i0 + i0w + (lane >> 2);
    const int iB = iA + 8;
    const int dcol = (lane & 3) * 2;
#pragma unroll
    for (int nd = 0; nd < 8; nd++) {
        int d0 = nd*8 + dcol;
        Yg[(size_t)(d0  ) * NPIX + iA] = o[nd][0] * inv0;
        Yg[(size_t)(d0+1) * NPIX + iA] = o[nd][1] * inv0;
        Yg[(size_t)(d0  ) * NPIX + iB] = o[nd][2] * inv1;
        Yg[(size_t)(d0+1) * NPIX + iB] = o[nd][3] * inv1;
    }
}

// =============================================================================
// Kernel 3: Y += BN(depthwise 3x3 conv(V)), pad=1.
// =============================================================================
__global__ __launch_bounds__(256) void pe_kernel(
    const float* __restrict__ w, const float* __restrict__ gg,
    const float* __restrict__ bb, const float* __restrict__ mm,
    const float* __restrict__ vv)
{
    const int tid = threadIdx.x;
    const int xx = tid & 63;
    const int yy = blockIdx.x * 4 + (tid >> 6);
    const int c  = blockIdx.y;
    const int b  = blockIdx.z;

    const float* V = g_V + (size_t)(b*DIMC + c) * NPIX;
    float wgt[9];
#pragma unroll
    for (int t = 0; t < 9; t++) wgt[t] = w[c*9 + t];
    float s    = gg[c] * rsqrtf(vv[c] + EPS);
    float beta = bb[c] - mm[c] * s;

    float acc = 0.f;
#pragma unroll
    for (int dy = -1; dy <= 1; dy++) {
        int y2 = yy + dy;
        if (y2 < 0 || y2 > 63) continue;
#pragma unroll
        for (int dx = -1; dx <= 1; dx++) {
            int x2 = xx + dx;
            if (x2 < 0 || x2 > 63) continue;
            acc = fmaf(wgt[(dy+1)*3 + (dx+1)], V[y2*64 + x2], acc);
        }
    }
    g_Y[(size_t)(b*DIMC + c) * NPIX + yy*64 + xx] += fmaf(acc, s, beta);
}

// =============================================================================
// Kernel 4: out = BN(P(256x256) @ Y).  f32x2 inner loop.
// =============================================================================
__global__ __launch_bounds__(256) void proj_kernel(
    const float* __restrict__ w, const float* __restrict__ gg,
    const float* __restrict__ bb, const float* __restrict__ mm,
    const float* __restrict__ vv, float* __restrict__ out)
{
    __shared__ float Wt[16*WS];
    __shared__ float Xt[16*XS];
    const int tid = threadIdx.x;
    const int n0 = blockIdx.x * 64;
    const int c0 = blockIdx.y * 64;
    const int b  = blockIdx.z;
    const int tc = tid & 15, tn = tid >> 4;
    const int wrow = tid >> 2, wseg = tid & 3;
    const int xkk  = tid >> 4, xseg = tid & 15;

    const float* yb = g_Y + (size_t)b * DIMC * NPIX;

    F2 acc[4][2];
#pragma unroll
    for (int i = 0; i < 4; i++) { acc[i][0].u = 0ull; acc[i][1].u = 0ull; }

    for (int k0 = 0; k0 < DIMC; k0 += 16) {
        float4 w4 = *(const float4*)&w[(c0 + wrow) * DIMC + k0 + wseg * 4];
        float4 x4 = *(const float4*)&yb[(size_t)(k0 + xkk) * NPIX + n0 + xseg * 4];
        __syncthreads();
        Wt[(wseg*4+0)*WS + wrow] = w4.x;
        Wt[(wseg*4+1)*WS + wrow] = w4.y;
        Wt[(wseg*4+2)*WS + wrow] = w4.z;
        Wt[(wseg*4+3)*WS + wrow] = w4.w;
        *(float4*)&Xt[xkk*XS + xseg*4] = x4;
        __syncthreads();
#pragma unroll
        for (int kk = 0; kk < 16; kk++) {
            float4 a4 = *(const float4*)&Wt[kk*WS + tc*4];
            ulonglong2 bp = *(const ulonglong2*)&Xt[kk*XS + tn*4];
            float av[4] = {a4.x, a4.y, a4.z, a4.w};
#pragma unroll
            for (int i = 0; i < 4; i++) {
                u64 a2 = bcast2(av[i]);
                acc[i][0].u = ffma2(a2, bp.x, acc[i][0].u);
                acc[i][1].u = ffma2(a2, bp.y, acc[i][1].u);
            }
        }
    }

#pragma unroll
    for (int ii = 0; ii < 4; ii++) {
        int c = c0 + tc * 4 + ii;
        float s    = gg[c] * rsqrtf(vv[c] + EPS);
        float beta = bb[c] - mm[c] * s;
        float4 o;
        o.x = fmaf(acc[ii][0].f.x, s, beta);
        o.y = fmaf(acc[ii][0].f.y, s, beta);
        o.z = fmaf(acc[ii][1].f.x, s, beta);
        o.w = fmaf(acc[ii][1].f.y, s, beta);
        *(float4*)&out[(size_t)(b*DIMC + c) * NPIX + n0 + tn*4] = o;
    }
}

// =============================================================================
extern "C" void kernel_launch(void* const* d_in, const int* in_sizes, int n_in,
                              void* d_out, int out_size)
{
    const float* x      = (const float*)d_in[0];
    const float* qkv_w  = (const float*)d_in[1];
    const float* qkv_g  = (const float*)d_in[2];
    const float* qkv_b  = (const float*)d_in[3];
    const float* qkv_m  = (const float*)d_in[4];
    const float* qkv_v  = (const float*)d_in[5];
    const float* proj_w = (const float*)d_in[6];
    const float* proj_g = (const float*)d_in[7];
    const float* proj_b = (const float*)d_in[8];
    const float* proj_m = (const float*)d_in[9];
    const float* proj_v = (const float*)d_in[10];
    const float* pe_w   = (const float*)d_in[11];
    const float* pe_g   = (const float*)d_in[12];
    const float* pe_b   = (const float*)d_in[13];
    const float* pe_m   = (const float*)d_in[14];
    const float* pe_v   = (const float*)d_in[15];
    float* out = (float*)d_out;

    cudaFuncSetAttribute(attn_kernel, cudaFuncAttributeMaxDynamicSharedMemorySize,
                         ATT_SMEM_BYTES);

    qkv_kernel<<<dim3(NPIX/64, HIDDEN/64, BATCH), 256>>>(
        x, qkv_w, qkv_g, qkv_b, qkv_m, qkv_v);

    attn_kernel<<<dim3(NPIX/128, HEADS, BATCH), 256, ATT_SMEM_BYTES>>>();

    pe_kernel<<<dim3(16, DIMC, BATCH), 256>>>(pe_w, pe_g, pe_b, pe_m, pe_v);

    proj_kernel<<<dim3(NPIX/64, DIMC/64, BATCH), 256>>>(
        proj_w, proj_g, proj_b, proj_m, proj_v, out);
}

// round 13
// speedup vs baseline: 1.4679x; 1.4679x over previous
#include <cuda_runtime.h>
#include <cuda_bf16.h>
#include <math.h>

#define DIMC   256
#define NPIX   4096
#define HEADS  4
#define KD     32
#define HD     64
#define BATCH  2
#define HIDDEN 512
#define EPS    1e-5f
#define ATT_SCALE 0.17677669529663687f   // 32^-0.5

typedef unsigned long long u64;
typedef unsigned int u32;
union F2 { u64 u; float2 f; };

__device__ __forceinline__ u64 ffma2(u64 a, u64 b, u64 c) {
    u64 d; asm("fma.rn.f32x2 %0, %1, %2, %3;" : "=l"(d) : "l"(a), "l"(b), "l"(c)); return d;
}
__device__ __forceinline__ u64 bcast2(float x) { F2 t; t.f.x = x; t.f.y = x; return t.u; }

// ---------------- scratch (device globals; no allocation allowed) ------------
__device__ __nv_bfloat16 g_Qh[BATCH*HEADS*NPIX*KD];  // [b][h][n][k], scaled, hi
__device__ __nv_bfloat16 g_Ql[BATCH*HEADS*NPIX*KD];  //                        lo
__device__ __nv_bfloat16 g_Kh[BATCH*HEADS*NPIX*KD];
__device__ __nv_bfloat16 g_Kl[BATCH*HEADS*NPIX*KD];
__device__ float g_V [BATCH*DIMC*NPIX];              // [b][h*64+d][n]  fp32 (pe)
__device__ __nv_bfloat16 g_Vh[BATCH*DIMC*NPIX];      // split-bf16 V (attn)
__device__ __nv_bfloat16 g_Vl[BATCH*DIMC*NPIX];
__device__ float g_Y[BATCH*DIMC*NPIX];               // attn out + pe

// ---------------- helpers ----------------------------------------------------
__device__ __forceinline__ u32 smem_u32(const void* p) {
    u32 a; asm("{ .reg .u64 t; cvta.to.shared.u64 t, %1; cvt.u32.u64 %0, t; }" : "=r"(a) : "l"(p));
    return a;
}
__device__ __forceinline__ u32 packbf(float lo, float hi) {
    u32 r; asm("cvt.rn.bf16x2.f32 %0, %1, %2;" : "=r"(r) : "f"(hi), "f"(lo)); return r;
}
__device__ __forceinline__ float bhi(float x) {
    return __bfloat162float(__float2bfloat16_rn(x));
}
__device__ __forceinline__ void bsplit(float x, unsigned short &h, unsigned short &l) {
    __nv_bfloat16 hh = __float2bfloat16_rn(x);
    __nv_bfloat16 ll = __float2bfloat16_rn(x - __bfloat162float(hh));
    h = __bfloat16_as_ushort(hh); l = __bfloat16_as_ushort(ll);
}

#define LDSM_X4(r0,r1,r2,r3,a) \
    asm volatile("ldmatrix.sync.aligned.m8n8.x4.shared.b16 {%0,%1,%2,%3}, [%4];" \
        : "=r"(r0),"=r"(r1),"=r"(r2),"=r"(r3) : "r"(a))

__device__ __forceinline__ void mma16816(float* d, const u32* a, u32 b0, u32 b1) {
    asm volatile("mma.sync.aligned.m16n8k16.row.col.f32.bf16.bf16.f32 "
        "{%0,%1,%2,%3}, {%4,%5,%6,%7}, {%8,%9}, {%0,%1,%2,%3};"
        : "+f"(d[0]), "+f"(d[1]), "+f"(d[2]), "+f"(d[3])
        : "r"(a[0]), "r"(a[1]), "r"(a[2]), "r"(a[3]), "r"(b0), "r"(b1));
}

// =============================================================================
// Kernel 1: qkv = BN(W @ x); Q,K -> split-bf16 [n][k]; V -> fp32 + split-bf16.
// =============================================================================
#define WS 68
#define XS 68
__global__ __launch_bounds__(256) void qkv_kernel(
    const float* __restrict__ x, const float* __restrict__ w,
    const float* __restrict__ gg, const float* __restrict__ bb,
    const float* __restrict__ mm, const float* __restrict__ vv)
{
    __shared__ float Wt[16*WS];
    __shared__ float Xt[16*XS];
    const int tid = threadIdx.x;
    const int n0 = blockIdx.x * 64;
    const int c0 = blockIdx.y * 64;
    const int b  = blockIdx.z;
    const int tc = tid & 15, tn = tid >> 4;
    const int wrow = tid >> 2, wseg = tid & 3;
    const int xkk  = tid >> 4, xseg = tid & 15;

    const float* xb = x + (size_t)b * DIMC * NPIX;

    F2 acc[4][2];
#pragma unroll
    for (int i = 0; i < 4; i++) { acc[i][0].u = 0ull; acc[i][1].u = 0ull; }

    for (int k0 = 0; k0 < DIMC; k0 += 16) {
        float4 w4 = *(const float4*)&w[(c0 + wrow) * DIMC + k0 + wseg * 4];
        float4 x4 = *(const float4*)&xb[(size_t)(k0 + xkk) * NPIX + n0 + xseg * 4];
        __syncthreads();
        Wt[(wseg*4+0)*WS + wrow] = w4.x;
        Wt[(wseg*4+1)*WS + wrow] = w4.y;
        Wt[(wseg*4+2)*WS + wrow] = w4.z;
        Wt[(wseg*4+3)*WS + wrow] = w4.w;
        *(float4*)&Xt[xkk*XS + xseg*4] = x4;
        __syncthreads();
#pragma unroll
        for (int kk = 0; kk < 16; kk++) {
            float4 a4 = *(const float4*)&Wt[kk*WS + tc*4];
            ulonglong2 bp = *(const ulonglong2*)&Xt[kk*XS + tn*4];
            float av[4] = {a4.x, a4.y, a4.z, a4.w};
#pragma unroll
            for (int i = 0; i < 4; i++) {
                u64 a2 = bcast2(av[i]);
                acc[i][0].u = ffma2(a2, bp.x, acc[i][0].u);
                acc[i][1].u = ffma2(a2, bp.y, acc[i][1].u);
            }
        }
    }

#pragma unroll
    for (int ii = 0; ii < 4; ii++) {
        int c = c0 + tc * 4 + ii;
        float s    = gg[c] * rsqrtf(vv[c] + EPS);
        float beta = bb[c] - mm[c] * s;
        float vals[4];
        vals[0] = fmaf(acc[ii][0].f.x, s, beta);
        vals[1] = fmaf(acc[ii][0].f.y, s, beta);
        vals[2] = fmaf(acc[ii][1].f.x, s, beta);
        vals[3] = fmaf(acc[ii][1].f.y, s, beta);
        int h = c >> 7, off = c & 127;
        if (off < 64) {
            bool isq = off < 32;
            int k = off & 31;
            float sc = isq ? ATT_SCALE : 1.0f;
            unsigned short* Hd = (unsigned short*)(isq ? g_Qh : g_Kh);
            unsigned short* Ld = (unsigned short*)(isq ? g_Ql : g_Kl);
            size_t base = ((size_t)(b*HEADS + h) * NPIX + n0 + tn*4) * KD + k;
#pragma unroll
            for (int j = 0; j < 4; j++) {
                unsigned short hh, ll;
                bsplit(vals[j] * sc, hh, ll);
                Hd[base + (size_t)j*KD] = hh;
                Ld[base + (size_t)j*KD] = ll;
            }
        } else {
            size_t row = (size_t)(b*DIMC + h*HD + (off-64)) * NPIX + n0 + tn*4;
            *(float4*)&g_V[row] = make_float4(vals[0], vals[1], vals[2], vals[3]);
            float h0 = bhi(vals[0]), h1 = bhi(vals[1]);
            float h2 = bhi(vals[2]), h3 = bhi(vals[3]);
            *(uint2*)&g_Vh[row] = make_uint2(packbf(h0, h1), packbf(h2, h3));
            *(uint2*)&g_Vl[row] = make_uint2(packbf(vals[0]-h0, vals[1]-h1),
                                             packbf(vals[2]-h2, vals[3]-h3));
        }
    }
}

// =============================================================================
// Kernel 2: flash attention via mma.sync (bf16 split, 3-pass).  R11 structure:
//   75.8 KB smem (occupancy-safe), 2 syncs per j-tile, plain LDG/STS copies.
//   Deltas vs R11: V tiles preconverted (pure uint4 copies), ldmatrix.x4 frags.
// smem:
//   Qh/Ql: [128][32] bf16, row stride 80B  -> 10240 B each
//   Kh/Kl: [128][32] bf16, row stride 80B  -> 10240 B each
//   Vh/Vl: [64][128] bf16, row stride 272B -> 17408 B each
// =============================================================================
#define QH_O 0
#define QL_O 10240
#define KH_O 20480
#define KL_O 30720
#define VH_O 40960
#define VL_O 58368
#define ATT_SMEM_BYTES 75776
#define NJ 32

__global__ __launch_bounds__(256) void attn_kernel()
{
    extern __shared__ char smb[];
    const int tid  = threadIdx.x;
    const int wid  = tid >> 5;
    const int lane = tid & 31;
    const int ib = blockIdx.x, h = blockIdx.y, b = blockIdx.z;
    const int i0 = ib * 128;
    const size_t bh = (size_t)(b*HEADS + h);

    const __nv_bfloat16* Qhg = g_Qh + bh * NPIX * KD;
    const __nv_bfloat16* Qlg = g_Ql + bh * NPIX * KD;
    const __nv_bfloat16* Khg = g_Kh + bh * NPIX * KD;
    const __nv_bfloat16* Klg = g_Kl + bh * NPIX * KD;
    const __nv_bfloat16* Vhg = g_Vh + (size_t)(b*DIMC + h*HD) * NPIX;
    const __nv_bfloat16* Vlg = g_Vl + (size_t)(b*DIMC + h*HD) * NPIX;
    float* Yg = g_Y + (size_t)(b*DIMC + h*HD) * NPIX;

    const u32 sbase = smem_u32(smb);

    // ---- load Q tile (static across jt): 128 rows x 32 bf16 ----
#pragma unroll
    for (int t = tid; t < 512; t += 256) {
        int row = t >> 2, ch = t & 3;
        *(uint4*)(smb + QH_O + row*80 + ch*16) = *(const uint4*)&Qhg[(size_t)(i0+row)*KD + ch*8];
        *(uint4*)(smb + QL_O + row*80 + ch*16) = *(const uint4*)&Qlg[(size_t)(i0+row)*KD + ch*8];
    }
    __syncthreads();

    // ---- Q A-fragments (2 k-steps, hi/lo) via ldmatrix.x4 ----
    const int i0w = wid * 16;
    const int qrow = i0w + (lane & 7) + ((lane >> 3) & 1) * 8;
    const u32 qcb  = ((lane >> 4) & 1) * 16;
    u32 qh[2][4], ql[2][4];
#pragma unroll
    for (int ks = 0; ks < 2; ks++) {
        LDSM_X4(qh[ks][0], qh[ks][1], qh[ks][2], qh[ks][3],
                sbase + QH_O + qrow*80 + ks*32 + qcb);
        LDSM_X4(ql[ks][0], ql[ks][1], ql[ks][2], ql[ks][3],
                sbase + QL_O + qrow*80 + ks*32 + qcb);
    }

    // fragment lane addressing
    const u32 kfr = (lane & 7)*80  + (lane >> 3)*16;  // K: 4 mats span k=0..31 of 8 j-rows
    const u32 vfr = (lane & 7)*272 + (lane >> 3)*16;  // V: 4 mats span 32 j of 8 d-rows

    float o[8][4];
#pragma unroll
    for (int nd = 0; nd < 8; nd++)
#pragma unroll
        for (int e = 0; e < 4; e++) o[nd][e] = 0.f;
    float ls0 = 0.f, ls1 = 0.f;

    for (int jt = 0; jt < NJ; jt++) {
        const int j0 = jt * 128;
        __syncthreads();   // all warps done reading previous K/V tiles

        // ---- K tiles (uint4 copies) ----
#pragma unroll
        for (int t = tid; t < 512; t += 256) {
            int row = t >> 2, ch = t & 3;
            *(uint4*)(smb + KH_O + row*80 + ch*16) = *(const uint4*)&Khg[(size_t)(j0+row)*KD + ch*8];
            *(uint4*)(smb + KL_O + row*80 + ch*16) = *(const uint4*)&Klg[(size_t)(j0+row)*KD + ch*8];
        }
        // ---- V tiles (preconverted, uint4 copies) ----
#pragma unroll
        for (int t = tid; t < 1024; t += 256) {
            int d = t >> 4, ch = t & 15;
            *(uint4*)(smb + VH_O + d*272 + ch*16) = *(const uint4*)&Vhg[(size_t)d * NPIX + j0 + ch*8];
            *(uint4*)(smb + VL_O + d*272 + ch*16) = *(const uint4*)&Vlg[(size_t)d * NPIX + j0 + ch*8];
        }
        __syncthreads();

#pragma unroll
        for (int half = 0; half < 2; half++) {
            // ---- S = Q^T K over this 64-j half: 8 D-frags, 3-pass split ----
            float sd[8][4];
#pragma unroll
            for (int jn = 0; jn < 8; jn++)
#pragma unroll
                for (int e = 0; e < 4; e++) sd[jn][e] = 0.f;

            const u32 kh_b = sbase + KH_O + half*5120 + kfr;
            const u32 kl_b = sbase + KL_O + half*5120 + kfr;
#pragma unroll
            for (int jn = 0; jn < 8; jn++) {
                u32 k0,k1,k2,k3, l0,l1,l2,l3;
                LDSM_X4(k0,k1,k2,k3, kh_b + jn*640);
                LDSM_X4(l0,l1,l2,l3, kl_b + jn*640);
                mma16816(sd[jn], qh[0], k0, k1);
                mma16816(sd[jn], qh[1], k2, k3);
                mma16816(sd[jn], qh[0], l0, l1);
                mma16816(sd[jn], qh[1], l2, l3);
                mma16816(sd[jn], ql[0], k0, k1);
                mma16816(sd[jn], ql[1], k2, k3);
            }

            // ---- exp + row sums + P A-frags (hi/lo) ----
            u32 ph[4][4], pl[4][4];
#pragma unroll
            for (int jn = 0; jn < 8; jn++) {
                float p0 = __expf(sd[jn][0]);
                float p1 = __expf(sd[jn][1]);
                float p2 = __expf(sd[jn][2]);
                float p3 = __expf(sd[jn][3]);
                ls0 += p0 + p1;
                ls1 += p2 + p3;
                float h0 = bhi(p0), h1 = bhi(p1), h2 = bhi(p2), h3 = bhi(p3);
                int af = jn >> 1, sel = (jn & 1) * 2;
                ph[af][sel+0] = packbf(h0, h1);
                ph[af][sel+1] = packbf(h2, h3);
                pl[af][sel+0] = packbf(p0 - h0, p1 - h1);
                pl[af][sel+1] = packbf(p2 - h2, p3 - h3);
            }

            // ---- O += P V^T over this half ----
            const u32 vh_b = sbase + VH_O + half*128 + vfr;
            const u32 vl_b = sbase + VL_O + half*128 + vfr;
#pragma unroll
            for (int p = 0; p < 2; p++) {
#pragma unroll
                for (int nd = 0; nd < 8; nd++) {
                    u32 a0,a1,a2,a3, c0,c1,c2,c3;
                    LDSM_X4(a0,a1,a2,a3, vh_b + nd*2176 + p*64);
                    LDSM_X4(c0,c1,c2,c3, vl_b + nd*2176 + p*64);
                    mma16816(o[nd], ph[2*p],   a0, a1);
                    mma16816(o[nd], ph[2*p+1], a2, a3);
                    mma16816(o[nd], ph[2*p],   c0, c1);
                    mma16816(o[nd], ph[2*p+1], c2, c3);
                    mma16816(o[nd], pl[2*p],   a0, a1);
                    mma16816(o[nd], pl[2*p+1], a2, a3);
                }
            }
        }
    }

    // ---- row sums across the 4 lanes sharing each row ----
    ls0 += __shfl_xor_sync(0xFFFFFFFF, ls0, 1);
    ls0 += __shfl_xor_sync(0xFFFFFFFF, ls0, 2);
    ls1 += __shfl_xor_sync(0xFFFFFFFF, ls1, 1);
    ls1 += __shfl_xor_sync(0xFFFFFFFF, ls1, 2);
    float inv0 = 1.0f / ls0;
    float inv1 = 1.0f / ls1;

    // ---- store O ----
    const int iA = i0 + i0w + (lane >> 2);
    const int iB = iA + 8;
    const int dcol = (lane & 3) * 2;
#pragma unroll
    for (int nd = 0; nd < 8; nd++) {
        int d0 = nd*8 + dcol;
        Yg[(size_t)(d0  ) * NPIX + iA] = o[nd][0] * inv0;
        Yg[(size_t)(d0+1) * NPIX + iA] = o[nd][1] * inv0;
        Yg[(size_t)(d0  ) * NPIX + iB] = o[nd][2] * inv1;
        Yg[(size_t)(d0+1) * NPIX + iB] = o[nd][3] * inv1;
    }
}

// =============================================================================
// Kernel 3: Y += BN(depthwise 3x3 conv(V)), pad=1.
// =============================================================================
__global__ __launch_bounds__(256) void pe_kernel(
    const float* __restrict__ w, const float* __restrict__ gg,
    const float* __restrict__ bb, const float* __restrict__ mm,
    const float* __restrict__ vv)
{
    const int tid = threadIdx.x;
    const int xx = tid & 63;
    const int yy = blockIdx.x * 4 + (tid >> 6);
    const int c  = blockIdx.y;
    const int b  = blockIdx.z;

    const float* V = g_V + (size_t)(b*DIMC + c) * NPIX;
    float wgt[9];
#pragma unroll
    for (int t = 0; t < 9; t++) wgt[t] = w[c*9 + t];
    float s    = gg[c] * rsqrtf(vv[c] + EPS);
    float beta = bb[c] - mm[c] * s;

    float acc = 0.f;
#pragma unroll
    for (int dy = -1; dy <= 1; dy++) {
        int y2 = yy + dy;
        if (y2 < 0 || y2 > 63) continue;
#pragma unroll
        for (int dx = -1; dx <= 1; dx++) {
            int x2 = xx + dx;
            if (x2 < 0 || x2 > 63) continue;
            acc = fmaf(wgt[(dy+1)*3 + (dx+1)], V[y2*64 + x2], acc);
        }
    }
    g_Y[(size_t)(b*DIMC + c) * NPIX + yy*64 + xx] += fmaf(acc, s, beta);
}

// =============================================================================
// Kernel 4: out = BN(P(256x256) @ Y).  f32x2 inner loop.
// =============================================================================
__global__ __launch_bounds__(256) void proj_kernel(
    const float* __restrict__ w, const float* __restrict__ gg,
    const float* __restrict__ bb, const float* __restrict__ mm,
    const float* __restrict__ vv, float* __restrict__ out)
{
    __shared__ float Wt[16*WS];
    __shared__ float Xt[16*XS];
    const int tid = threadIdx.x;
    const int n0 = blockIdx.x * 64;
    const int c0 = blockIdx.y * 64;
    const int b  = blockIdx.z;
    const int tc = tid & 15, tn = tid >> 4;
    const int wrow = tid >> 2, wseg = tid & 3;
    const int xkk  = tid >> 4, xseg = tid & 15;

    const float* yb = g_Y + (size_t)b * DIMC * NPIX;

    F2 acc[4][2];
#pragma unroll
    for (int i = 0; i < 4; i++) { acc[i][0].u = 0ull; acc[i][1].u = 0ull; }

    for (int k0 = 0; k0 < DIMC; k0 += 16) {
        float4 w4 = *(const float4*)&w[(c0 + wrow) * DIMC + k0 + wseg * 4];
        float4 x4 = *(const float4*)&yb[(size_t)(k0 + xkk) * NPIX + n0 + xseg * 4];
        __syncthreads();
        Wt[(wseg*4+0)*WS + wrow] = w4.x;
        Wt[(wseg*4+1)*WS + wrow] = w4.y;
        Wt[(wseg*4+2)*WS + wrow] = w4.z;
        Wt[(wseg*4+3)*WS + wrow] = w4.w;
        *(float4*)&Xt[xkk*XS + xseg*4] = x4;
        __syncthreads();
#pragma unroll
        for (int kk = 0; kk < 16; kk++) {
            float4 a4 = *(const float4*)&Wt[kk*WS + tc*4];
            ulonglong2 bp = *(const ulonglong2*)&Xt[kk*XS + tn*4];
            float av[4] = {a4.x, a4.y, a4.z, a4.w};
#pragma unroll
            for (int i = 0; i < 4; i++) {
                u64 a2 = bcast2(av[i]);
                acc[i][0].u = ffma2(a2, bp.x, acc[i][0].u);
                acc[i][1].u = ffma2(a2, bp.y, acc[i][1].u);
            }
        }
    }

#pragma unroll
    for (int ii = 0; ii < 4; ii++) {
        int c = c0 + tc * 4 + ii;
        float s    = gg[c] * rsqrtf(vv[c] + EPS);
        float beta = bb[c] - mm[c] * s;
        float4 o;
        o.x = fmaf(acc[ii][0].f.x, s, beta);
        o.y = fmaf(acc[ii][0].f.y, s, beta);
        o.z = fmaf(acc[ii][1].f.x, s, beta);
        o.w = fmaf(acc[ii][1].f.y, s, beta);
        *(float4*)&out[(size_t)(b*DIMC + c) * NPIX + n0 + tn*4] = o;
    }
}

// =============================================================================
extern "C" void kernel_launch(void* const* d_in, const int* in_sizes, int n_in,
                              void* d_out, int out_size)
{
    const float* x      = (const float*)d_in[0];
    const float* qkv_w  = (const float*)d_in[1];
    const float* qkv_g  = (const float*)d_in[2];
    const float* qkv_b  = (const float*)d_in[3];
    const float* qkv_m  = (const float*)d_in[4];
    const float* qkv_v  = (const float*)d_in[5];
    const float* proj_w = (const float*)d_in[6];
    const float* proj_g = (const float*)d_in[7];
    const float* proj_b = (const float*)d_in[8];
    const float* proj_m = (const float*)d_in[9];
    const float* proj_v = (const float*)d_in[10];
    const float* pe_w   = (const float*)d_in[11];
    const float* pe_g   = (const float*)d_in[12];
    const float* pe_b   = (const float*)d_in[13];
    const float* pe_m   = (const float*)d_in[14];
    const float* pe_v   = (const float*)d_in[15];
    float* out = (float*)d_out;

    cudaFuncSetAttribute(attn_kernel, cudaFuncAttributeMaxDynamicSharedMemorySize,
                         ATT_SMEM_BYTES);

    qkv_kernel<<<dim3(NPIX/64, HIDDEN/64, BATCH), 256>>>(
        x, qkv_w, qkv_g, qkv_b, qkv_m, qkv_v);

    attn_kernel<<<dim3(NPIX/128, HEADS, BATCH), 256, ATT_SMEM_BYTES>>>();

    pe_kernel<<<dim3(16, DIMC, BATCH), 256>>>(pe_w, pe_g, pe_b, pe_m, pe_v);

    proj_kernel<<<dim3(NPIX/64, DIMC/64, BATCH), 256>>>(
        proj_w, proj_g, proj_b, proj_m, proj_v, out);
}

// round 14
// speedup vs baseline: 2.0388x; 1.3889x over previous
#include <cuda_runtime.h>
#include <cuda_bf16.h>
#include <math.h>

#define DIMC   256
#define NPIX   4096
#define HEADS  4
#define KD     32
#define HD     64
#define BATCH  2
#define HIDDEN 512
#define EPS    1e-5f
#define ATT_SCALE 0.17677669529663687f   // 32^-0.5

typedef unsigned long long u64;
typedef unsigned int u32;
union F2 { u64 u; float2 f; };

__device__ __forceinline__ u64 ffma2(u64 a, u64 b, u64 c) {
    u64 d; asm("fma.rn.f32x2 %0, %1, %2, %3;" : "=l"(d) : "l"(a), "l"(b), "l"(c)); return d;
}
__device__ __forceinline__ u64 bcast2(float x) { F2 t; t.f.x = x; t.f.y = x; return t.u; }

// ---------------- scratch (device globals; no allocation allowed) ------------
__device__ __nv_bfloat16 g_Qh[BATCH*HEADS*NPIX*KD];  // [b][h][n][k], scaled, hi
__device__ __nv_bfloat16 g_Ql[BATCH*HEADS*NPIX*KD];  //                        lo
__device__ __nv_bfloat16 g_Kh[BATCH*HEADS*NPIX*KD];
__device__ __nv_bfloat16 g_Kl[BATCH*HEADS*NPIX*KD];
__device__ float g_V [BATCH*DIMC*NPIX];              // [b][h*64+d][n] fp32 (pe)
__device__ __nv_bfloat16 g_Vh[BATCH*DIMC*NPIX];      // bf16 V (attn PV)
__device__ float g_Y[BATCH*DIMC*NPIX];               // attn out + pe

// ---------------- helpers ----------------------------------------------------
__device__ __forceinline__ u32 smem_u32(const void* p) {
    u32 a; asm("{ .reg .u64 t; cvta.to.shared.u64 t, %1; cvt.u32.u64 %0, t; }" : "=r"(a) : "l"(p));
    return a;
}
__device__ __forceinline__ u32 packbf(float lo, float hi) {
    u32 r; asm("cvt.rn.bf16x2.f32 %0, %1, %2;" : "=r"(r) : "f"(hi), "f"(lo)); return r;
}
__device__ __forceinline__ void bsplit(float x, unsigned short &h, unsigned short &l) {
    __nv_bfloat16 hh = __float2bfloat16_rn(x);
    __nv_bfloat16 ll = __float2bfloat16_rn(x - __bfloat162float(hh));
    h = __bfloat16_as_ushort(hh); l = __bfloat16_as_ushort(ll);
}

#define LDSM_X4(r0,r1,r2,r3,a) \
    asm volatile("ldmatrix.sync.aligned.m8n8.x4.shared.b16 {%0,%1,%2,%3}, [%4];" \
        : "=r"(r0),"=r"(r1),"=r"(r2),"=r"(r3) : "r"(a))

__device__ __forceinline__ void mma16816(float* d, const u32* a, u32 b0, u32 b1) {
    asm volatile("mma.sync.aligned.m16n8k16.row.col.f32.bf16.bf16.f32 "
        "{%0,%1,%2,%3}, {%4,%5,%6,%7}, {%8,%9}, {%0,%1,%2,%3};"
        : "+f"(d[0]), "+f"(d[1]), "+f"(d[2]), "+f"(d[3])
        : "r"(a[0]), "r"(a[1]), "r"(a[2]), "r"(a[3]), "r"(b0), "r"(b1));
}

// =============================================================================
// Kernel 1: qkv = BN(W @ x); Q,K -> split-bf16 [n][k]; V -> fp32 + bf16.
// =============================================================================
#define WS 68
#define XS 68
__global__ __launch_bounds__(256) void qkv_kernel(
    const float* __restrict__ x, const float* __restrict__ w,
    const float* __restrict__ gg, const float* __restrict__ bb,
    const float* __restrict__ mm, const float* __restrict__ vv)
{
    __shared__ float Wt[16*WS];
    __shared__ float Xt[16*XS];
    const int tid = threadIdx.x;
    const int n0 = blockIdx.x * 64;
    const int c0 = blockIdx.y * 64;
    const int b  = blockIdx.z;
    const int tc = tid & 15, tn = tid >> 4;
    const int wrow = tid >> 2, wseg = tid & 3;
    const int xkk  = tid >> 4, xseg = tid & 15;

    const float* xb = x + (size_t)b * DIMC * NPIX;

    F2 acc[4][2];
#pragma unroll
    for (int i = 0; i < 4; i++) { acc[i][0].u = 0ull; acc[i][1].u = 0ull; }

    for (int k0 = 0; k0 < DIMC; k0 += 16) {
        float4 w4 = *(const float4*)&w[(c0 + wrow) * DIMC + k0 + wseg * 4];
        float4 x4 = *(const float4*)&xb[(size_t)(k0 + xkk) * NPIX + n0 + xseg * 4];
        __syncthreads();
        Wt[(wseg*4+0)*WS + wrow] = w4.x;
        Wt[(wseg*4+1)*WS + wrow] = w4.y;
        Wt[(wseg*4+2)*WS + wrow] = w4.z;
        Wt[(wseg*4+3)*WS + wrow] = w4.w;
        *(float4*)&Xt[xkk*XS + xseg*4] = x4;
        __syncthreads();
#pragma unroll
        for (int kk = 0; kk < 16; kk++) {
            float4 a4 = *(const float4*)&Wt[kk*WS + tc*4];
            ulonglong2 bp = *(const ulonglong2*)&Xt[kk*XS + tn*4];
            float av[4] = {a4.x, a4.y, a4.z, a4.w};
#pragma unroll
            for (int i = 0; i < 4; i++) {
                u64 a2 = bcast2(av[i]);
                acc[i][0].u = ffma2(a2, bp.x, acc[i][0].u);
                acc[i][1].u = ffma2(a2, bp.y, acc[i][1].u);
            }
        }
    }

#pragma unroll
    for (int ii = 0; ii < 4; ii++) {
        int c = c0 + tc * 4 + ii;
        float s    = gg[c] * rsqrtf(vv[c] + EPS);
        float beta = bb[c] - mm[c] * s;
        float vals[4];
        vals[0] = fmaf(acc[ii][0].f.x, s, beta);
        vals[1] = fmaf(acc[ii][0].f.y, s, beta);
        vals[2] = fmaf(acc[ii][1].f.x, s, beta);
        vals[3] = fmaf(acc[ii][1].f.y, s, beta);
        int h = c >> 7, off = c & 127;
        if (off < 64) {
            bool isq = off < 32;
            int k = off & 31;
            float sc = isq ? ATT_SCALE : 1.0f;
            unsigned short* Hd = (unsigned short*)(isq ? g_Qh : g_Kh);
            unsigned short* Ld = (unsigned short*)(isq ? g_Ql : g_Kl);
            size_t base = ((size_t)(b*HEADS + h) * NPIX + n0 + tn*4) * KD + k;
#pragma unroll
            for (int j = 0; j < 4; j++) {
                unsigned short hh, ll;
                bsplit(vals[j] * sc, hh, ll);
                Hd[base + (size_t)j*KD] = hh;
                Ld[base + (size_t)j*KD] = ll;
            }
        } else {
            size_t row = (size_t)(b*DIMC + h*HD + (off-64)) * NPIX + n0 + tn*4;
            *(float4*)&g_V[row] = make_float4(vals[0], vals[1], vals[2], vals[3]);
            *(uint2*)&g_Vh[row] = make_uint2(packbf(vals[0], vals[1]),
                                             packbf(vals[2], vals[3]));
        }
    }
}

// =============================================================================
// Kernel 2: flash attention via mma.sync.
//   S = Q^T K in split-bf16 3-pass (accuracy-critical).
//   P, V in plain bf16-rn (rounding is zero-mean; output is a softmax-weighted
//   average -> ~1e-4 relative error, fp32-exact denominator).
// smem: Qh/Ql [128][32]@80B, Kh/Kl [128][32]@80B, Vh [64][128]@272B = 58368 B.
// =============================================================================
#define QH_O 0
#define QL_O 10240
#define KH_O 20480
#define KL_O 30720
#define VH_O 40960
#define ATT_SMEM_BYTES 58368
#define NJ 32

__global__ __launch_bounds__(256) void attn_kernel()
{
    extern __shared__ char smb[];
    const int tid  = threadIdx.x;
    const int wid  = tid >> 5;
    const int lane = tid & 31;
    const int ib = blockIdx.x, h = blockIdx.y, b = blockIdx.z;
    const int i0 = ib * 128;
    const size_t bh = (size_t)(b*HEADS + h);

    const __nv_bfloat16* Qhg = g_Qh + bh * NPIX * KD;
    const __nv_bfloat16* Qlg = g_Ql + bh * NPIX * KD;
    const __nv_bfloat16* Khg = g_Kh + bh * NPIX * KD;
    const __nv_bfloat16* Klg = g_Kl + bh * NPIX * KD;
    const __nv_bfloat16* Vhg = g_Vh + (size_t)(b*DIMC + h*HD) * NPIX;
    float* Yg = g_Y + (size_t)(b*DIMC + h*HD) * NPIX;

    const u32 sbase = smem_u32(smb);

    // ---- load Q tile (static across jt): 128 rows x 32 bf16 ----
#pragma unroll
    for (int t = tid; t < 512; t += 256) {
        int row = t >> 2, ch = t & 3;
        *(uint4*)(smb + QH_O + row*80 + ch*16) = *(const uint4*)&Qhg[(size_t)(i0+row)*KD + ch*8];
        *(uint4*)(smb + QL_O + row*80 + ch*16) = *(const uint4*)&Qlg[(size_t)(i0+row)*KD + ch*8];
    }
    __syncthreads();

    // ---- Q A-fragments (2 k-steps, hi/lo) via ldmatrix.x4 ----
    const int i0w = wid * 16;
    const int qrow = i0w + (lane & 7) + ((lane >> 3) & 1) * 8;
    const u32 qcb  = ((lane >> 4) & 1) * 16;
    u32 qh[2][4], ql[2][4];
#pragma unroll
    for (int ks = 0; ks < 2; ks++) {
        LDSM_X4(qh[ks][0], qh[ks][1], qh[ks][2], qh[ks][3],
                sbase + QH_O + qrow*80 + ks*32 + qcb);
        LDSM_X4(ql[ks][0], ql[ks][1], ql[ks][2], ql[ks][3],
                sbase + QL_O + qrow*80 + ks*32 + qcb);
    }

    // fragment lane addressing
    const u32 kfr = (lane & 7)*80  + (lane >> 3)*16;
    const u32 vfr = (lane & 7)*272 + (lane >> 3)*16;

    float o[8][4];
#pragma unroll
    for (int nd = 0; nd < 8; nd++)
#pragma unroll
        for (int e = 0; e < 4; e++) o[nd][e] = 0.f;
    float ls0 = 0.f, ls1 = 0.f;

    for (int jt = 0; jt < NJ; jt++) {
        const int j0 = jt * 128;
        __syncthreads();   // all warps done reading previous K/V tiles

        // ---- K tiles (uint4 copies) ----
#pragma unroll
        for (int t = tid; t < 512; t += 256) {
            int row = t >> 2, ch = t & 3;
            *(uint4*)(smb + KH_O + row*80 + ch*16) = *(const uint4*)&Khg[(size_t)(j0+row)*KD + ch*8];
            *(uint4*)(smb + KL_O + row*80 + ch*16) = *(const uint4*)&Klg[(size_t)(j0+row)*KD + ch*8];
        }
        // ---- V tile (bf16, uint4 copies) ----
#pragma unroll
        for (int t = tid; t < 1024; t += 256) {
            int d = t >> 4, ch = t & 15;
            *(uint4*)(smb + VH_O + d*272 + ch*16) = *(const uint4*)&Vhg[(size_t)d * NPIX + j0 + ch*8];
        }
        __syncthreads();

#pragma unroll
        for (int half = 0; half < 2; half++) {
            // ---- S = Q^T K over this 64-j half: 8 D-frags, 3-pass split ----
            float sd[8][4];
#pragma unroll
            for (int jn = 0; jn < 8; jn++)
#pragma unroll
                for (int e = 0; e < 4; e++) sd[jn][e] = 0.f;

            const u32 kh_b = sbase + KH_O + half*5120 + kfr;
            const u32 kl_b = sbase + KL_O + half*5120 + kfr;
#pragma unroll
            for (int jn = 0; jn < 8; jn++) {
                u32 k0,k1,k2,k3, l0,l1,l2,l3;
                LDSM_X4(k0,k1,k2,k3, kh_b + jn*640);
                LDSM_X4(l0,l1,l2,l3, kl_b + jn*640);
                mma16816(sd[jn], qh[0], k0, k1);
                mma16816(sd[jn], qh[1], k2, k3);
                mma16816(sd[jn], qh[0], l0, l1);
                mma16816(sd[jn], qh[1], l2, l3);
                mma16816(sd[jn], ql[0], k0, k1);
                mma16816(sd[jn], ql[1], k2, k3);
            }

            // ---- exp + row sums + P A-frags (bf16-rn) ----
            u32 ph[4][4];
#pragma unroll
            for (int jn = 0; jn < 8; jn++) {
                float p0 = __expf(sd[jn][0]);
                float p1 = __expf(sd[jn][1]);
                float p2 = __expf(sd[jn][2]);
                float p3 = __expf(sd[jn][3]);
                ls0 += p0 + p1;
                ls1 += p2 + p3;
                int af = jn >> 1, sel = (jn & 1) * 2;
                ph[af][sel+0] = packbf(p0, p1);
                ph[af][sel+1] = packbf(p2, p3);
            }

            // ---- O += P V^T over this half (V bf16) ----
            const u32 vh_b = sbase + VH_O + half*128 + vfr;
#pragma unroll
            for (int p = 0; p < 2; p++) {
#pragma unroll
                for (int nd = 0; nd < 8; nd++) {
                    u32 a0,a1,a2,a3;
                    LDSM_X4(a0,a1,a2,a3, vh_b + nd*2176 + p*64);
                    mma16816(o[nd], ph[2*p],   a0, a1);
                    mma16816(o[nd], ph[2*p+1], a2, a3);
                }
            }
        }
    }

    // ---- row sums across the 4 lanes sharing each row ----
    ls0 += __shfl_xor_sync(0xFFFFFFFF, ls0, 1);
    ls0 += __shfl_xor_sync(0xFFFFFFFF, ls0, 2);
    ls1 += __shfl_xor_sync(0xFFFFFFFF, ls1, 1);
    ls1 += __shfl_xor_sync(0xFFFFFFFF, ls1, 2);
    float inv0 = 1.0f / ls0;
    float inv1 = 1.0f / ls1;

    // ---- store O ----
    const int iA = i0 + i0w + (lane >> 2);
    const int iB = iA + 8;
    const int dcol = (lane & 3) * 2;
#pragma unroll
    for (int nd = 0; nd < 8; nd++) {
        int d0 = nd*8 + dcol;
        Yg[(size_t)(d0  ) * NPIX + iA] = o[nd][0] * inv0;
        Yg[(size_t)(d0+1) * NPIX + iA] = o[nd][1] * inv0;
        Yg[(size_t)(d0  ) * NPIX + iB] = o[nd][2] * inv1;
        Yg[(size_t)(d0+1) * NPIX + iB] = o[nd][3] * inv1;
    }
}

// =============================================================================
// Kernel 3: Y += BN(depthwise 3x3 conv(V)), pad=1.
// =============================================================================
__global__ __launch_bounds__(256) void pe_kernel(
    const float* __restrict__ w, const float* __restrict__ gg,
    const float* __restrict__ bb, const float* __restrict__ mm,
    const float* __restrict__ vv)
{
    const int tid = threadIdx.x;
    const int xx = tid & 63;
    const int yy = blockIdx.x * 4 + (tid >> 6);
    const int c  = blockIdx.y;
    const int b  = blockIdx.z;

    const float* V = g_V + (size_t)(b*DIMC + c) * NPIX;
    float wgt[9];
#pragma unroll
    for (int t = 0; t < 9; t++) wgt[t] = w[c*9 + t];
    float s    = gg[c] * rsqrtf(vv[c] + EPS);
    float beta = bb[c] - mm[c] * s;

    float acc = 0.f;
#pragma unroll
    for (int dy = -1; dy <= 1; dy++) {
        int y2 = yy + dy;
        if (y2 < 0 || y2 > 63) continue;
#pragma unroll
        for (int dx = -1; dx <= 1; dx++) {
            int x2 = xx + dx;
            if (x2 < 0 || x2 > 63) continue;
            acc = fmaf(wgt[(dy+1)*3 + (dx+1)], V[y2*64 + x2], acc);
        }
    }
    g_Y[(size_t)(b*DIMC + c) * NPIX + yy*64 + xx] += fmaf(acc, s, beta);
}

// =============================================================================
// Kernel 4: out = BN(P(256x256) @ Y).  f32x2 inner loop.
// =============================================================================
__global__ __launch_bounds__(256) void proj_kernel(
    const float* __restrict__ w, const float* __restrict__ gg,
    const float* __restrict__ bb, const float* __restrict__ mm,
    const float* __restrict__ vv, float* __restrict__ out)
{
    __shared__ float Wt[16*WS];
    __shared__ float Xt[16*XS];
    const int tid = threadIdx.x;
    const int n0 = blockIdx.x * 64;
    const int c0 = blockIdx.y * 64;
    const int b  = blockIdx.z;
    const int tc = tid & 15, tn = tid >> 4;
    const int wrow = tid >> 2, wseg = tid & 3;
    const int xkk  = tid >> 4, xseg = tid & 15;

    const float* yb = g_Y + (size_t)b * DIMC * NPIX;

    F2 acc[4][2];
#pragma unroll
    for (int i = 0; i < 4; i++) { acc[i][0].u = 0ull; acc[i][1].u = 0ull; }

    for (int k0 = 0; k0 < DIMC; k0 += 16) {
        float4 w4 = *(const float4*)&w[(c0 + wrow) * DIMC + k0 + wseg * 4];
        float4 x4 = *(const float4*)&yb[(size_t)(k0 + xkk) * NPIX + n0 + xseg * 4];
        __syncthreads();
        Wt[(wseg*4+0)*WS + wrow] = w4.x;
        Wt[(wseg*4+1)*WS + wrow] = w4.y;
        Wt[(wseg*4+2)*WS + wrow] = w4.z;
        Wt[(wseg*4+3)*WS + wrow] = w4.w;
        *(float4*)&Xt[xkk*XS + xseg*4] = x4;
        __syncthreads();
#pragma unroll
        for (int kk = 0; kk < 16; kk++) {
            float4 a4 = *(const float4*)&Wt[kk*WS + tc*4];
            ulonglong2 bp = *(const ulonglong2*)&Xt[kk*XS + tn*4];
            float av[4] = {a4.x, a4.y, a4.z, a4.w};
#pragma unroll
            for (int i = 0; i < 4; i++) {
                u64 a2 = bcast2(av[i]);
                acc[i][0].u = ffma2(a2, bp.x, acc[i][0].u);
                acc[i][1].u = ffma2(a2, bp.y, acc[i][1].u);
            }
        }
    }

#pragma unroll
    for (int ii = 0; ii < 4; ii++) {
        int c = c0 + tc * 4 + ii;
        float s    = gg[c] * rsqrtf(vv[c] + EPS);
        float beta = bb[c] - mm[c] * s;
        float4 o;
        o.x = fmaf(acc[ii][0].f.x, s, beta);
        o.y = fmaf(acc[ii][0].f.y, s, beta);
        o.z = fmaf(acc[ii][1].f.x, s, beta);
        o.w = fmaf(acc[ii][1].f.y, s, beta);
        *(float4*)&out[(size_t)(b*DIMC + c) * NPIX + n0 + tn*4] = o;
    }
}

// =============================================================================
extern "C" void kernel_launch(void* const* d_in, const int* in_sizes, int n_in,
                              void* d_out, int out_size)
{
    const float* x      = (const float*)d_in[0];
    const float* qkv_w  = (const float*)d_in[1];
    const float* qkv_g  = (const float*)d_in[2];
    const float* qkv_b  = (const float*)d_in[3];
    const float* qkv_m  = (const float*)d_in[4];
    const float* qkv_v  = (const float*)d_in[5];
    const float* proj_w = (const float*)d_in[6];
    const float* proj_g = (const float*)d_in[7];
    const float* proj_b = (const float*)d_in[8];
    const float* proj_m = (const float*)d_in[9];
    const float* proj_v = (const float*)d_in[10];
    const float* pe_w   = (const float*)d_in[11];
    const float* pe_g   = (const float*)d_in[12];
    const float* pe_b   = (const float*)d_in[13];
    const float* pe_m   = (const float*)d_in[14];
    const float* pe_v   = (const float*)d_in[15];
    float* out = (float*)d_out;

    cudaFuncSetAttribute(attn_kernel, cudaFuncAttributeMaxDynamicSharedMemorySize,
                         ATT_SMEM_BYTES);

    qkv_kernel<<<dim3(NPIX/64, HIDDEN/64, BATCH), 256>>>(
        x, qkv_w, qkv_g, qkv_b, qkv_m, qkv_v);

    attn_kernel<<<dim3(NPIX/128, HEADS, BATCH), 256, ATT_SMEM_BYTES>>>();

    pe_kernel<<<dim3(16, DIMC, BATCH), 256>>>(pe_w, pe_g, pe_b, pe_m, pe_v);

    proj_kernel<<<dim3(NPIX/64, DIMC/64, BATCH), 256>>>(
        proj_w, proj_g, proj_b, proj_m, proj_v, out);
}

// round 15
// speedup vs baseline: 2.6025x; 1.2765x over previous
#include <cuda_runtime.h>
#include <cuda_bf16.h>
#include <math.h>

#define DIMC   256
#define NPIX   4096
#define HEADS  4
#define KD     32
#define HD     64
#define BATCH  2
#define HIDDEN 512
#define EPS    1e-5f
#define ATT_SCALE 0.17677669529663687f   // 32^-0.5

typedef unsigned long long u64;
typedef unsigned int u32;
union F2 { u64 u; float2 f; };

__device__ __forceinline__ u64 ffma2(u64 a, u64 b, u64 c) {
    u64 d; asm("fma.rn.f32x2 %0, %1, %2, %3;" : "=l"(d) : "l"(a), "l"(b), "l"(c)); return d;
}
__device__ __forceinline__ u64 bcast2(float x) { F2 t; t.f.x = x; t.f.y = x; return t.u; }

// ---------------- scratch (device globals; no allocation allowed) ------------
__device__ __nv_bfloat16 g_Qh[BATCH*HEADS*NPIX*KD];  // [b][h][n][k], scaled, hi
__device__ __nv_bfloat16 g_Ql[BATCH*HEADS*NPIX*KD];  //                        lo
__device__ __nv_bfloat16 g_Kh[BATCH*HEADS*NPIX*KD];
__device__ __nv_bfloat16 g_Kl[BATCH*HEADS*NPIX*KD];
__device__ float g_V [BATCH*DIMC*NPIX];              // [b][h*64+d][n] fp32 (pe)
__device__ __nv_bfloat16 g_Vh[BATCH*DIMC*NPIX];      // bf16 V (attn PV)
__device__ float g_Y[BATCH*DIMC*NPIX];               // attn out + pe
__device__ __nv_bfloat16 g_Wph[DIMC*DIMC];           // proj W * bn_scale, hi
__device__ __nv_bfloat16 g_Wpl[DIMC*DIMC];           //                    lo
__device__ float g_betap[DIMC];                      // proj bn beta

// ---------------- helpers ----------------------------------------------------
__device__ __forceinline__ u32 smem_u32(const void* p) {
    u32 a; asm("{ .reg .u64 t; cvta.to.shared.u64 t, %1; cvt.u32.u64 %0, t; }" : "=r"(a) : "l"(p));
    return a;
}
__device__ __forceinline__ u32 packbf(float lo, float hi) {
    u32 r; asm("cvt.rn.bf16x2.f32 %0, %1, %2;" : "=r"(r) : "f"(hi), "f"(lo)); return r;
}
__device__ __forceinline__ float bhi(float x) {
    return __bfloat162float(__float2bfloat16_rn(x));
}
__device__ __forceinline__ void bsplit(float x, unsigned short &h, unsigned short &l) {
    __nv_bfloat16 hh = __float2bfloat16_rn(x);
    __nv_bfloat16 ll = __float2bfloat16_rn(x - __bfloat162float(hh));
    h = __bfloat16_as_ushort(hh); l = __bfloat16_as_ushort(ll);
}
__device__ __forceinline__ void cpa16(u32 dst, const void* src) {
    asm volatile("cp.async.cg.shared.global [%0], [%1], 16;" :: "r"(dst), "l"(src));
}

#define LDSM_X4(r0,r1,r2,r3,a) \
    asm volatile("ldmatrix.sync.aligned.m8n8.x4.shared.b16 {%0,%1,%2,%3}, [%4];" \
        : "=r"(r0),"=r"(r1),"=r"(r2),"=r"(r3) : "r"(a))
#define LDSM_X4T(r0,r1,r2,r3,a) \
    asm volatile("ldmatrix.sync.aligned.m8n8.x4.trans.shared.b16 {%0,%1,%2,%3}, [%4];" \
        : "=r"(r0),"=r"(r1),"=r"(r2),"=r"(r3) : "r"(a))

__device__ __forceinline__ void mma16816(float* d, const u32* a, u32 b0, u32 b1) {
    asm volatile("mma.sync.aligned.m16n8k16.row.col.f32.bf16.bf16.f32 "
        "{%0,%1,%2,%3}, {%4,%5,%6,%7}, {%8,%9}, {%0,%1,%2,%3};"
        : "+f"(d[0]), "+f"(d[1]), "+f"(d[2]), "+f"(d[3])
        : "r"(a[0]), "r"(a[1]), "r"(a[2]), "r"(a[3]), "r"(b0), "r"(b1));
}

// =============================================================================
// Kernel 1: qkv = BN(W @ x); Q,K -> split-bf16 [n][k]; V -> fp32 + bf16.
// =============================================================================
#define WS 68
#define XS 68
__global__ __launch_bounds__(256) void qkv_kernel(
    const float* __restrict__ x, const float* __restrict__ w,
    const float* __restrict__ gg, const float* __restrict__ bb,
    const float* __restrict__ mm, const float* __restrict__ vv)
{
    __shared__ float Wt[16*WS];
    __shared__ float Xt[16*XS];
    const int tid = threadIdx.x;
    const int n0 = blockIdx.x * 64;
    const int c0 = blockIdx.y * 64;
    const int b  = blockIdx.z;
    const int tc = tid & 15, tn = tid >> 4;
    const int wrow = tid >> 2, wseg = tid & 3;
    const int xkk  = tid >> 4, xseg = tid & 15;

    const float* xb = x + (size_t)b * DIMC * NPIX;

    F2 acc[4][2];
#pragma unroll
    for (int i = 0; i < 4; i++) { acc[i][0].u = 0ull; acc[i][1].u = 0ull; }

    for (int k0 = 0; k0 < DIMC; k0 += 16) {
        float4 w4 = *(const float4*)&w[(c0 + wrow) * DIMC + k0 + wseg * 4];
        float4 x4 = *(const float4*)&xb[(size_t)(k0 + xkk) * NPIX + n0 + xseg * 4];
        __syncthreads();
        Wt[(wseg*4+0)*WS + wrow] = w4.x;
        Wt[(wseg*4+1)*WS + wrow] = w4.y;
        Wt[(wseg*4+2)*WS + wrow] = w4.z;
        Wt[(wseg*4+3)*WS + wrow] = w4.w;
        *(float4*)&Xt[xkk*XS + xseg*4] = x4;
        __syncthreads();
#pragma unroll
        for (int kk = 0; kk < 16; kk++) {
            float4 a4 = *(const float4*)&Wt[kk*WS + tc*4];
            ulonglong2 bp = *(const ulonglong2*)&Xt[kk*XS + tn*4];
            float av[4] = {a4.x, a4.y, a4.z, a4.w};
#pragma unroll
            for (int i = 0; i < 4; i++) {
                u64 a2 = bcast2(av[i]);
                acc[i][0].u = ffma2(a2, bp.x, acc[i][0].u);
                acc[i][1].u = ffma2(a2, bp.y, acc[i][1].u);
            }
        }
    }

#pragma unroll
    for (int ii = 0; ii < 4; ii++) {
        int c = c0 + tc * 4 + ii;
        float s    = gg[c] * rsqrtf(vv[c] + EPS);
        float beta = bb[c] - mm[c] * s;
        float vals[4];
        vals[0] = fmaf(acc[ii][0].f.x, s, beta);
        vals[1] = fmaf(acc[ii][0].f.y, s, beta);
        vals[2] = fmaf(acc[ii][1].f.x, s, beta);
        vals[3] = fmaf(acc[ii][1].f.y, s, beta);
        int h = c >> 7, off = c & 127;
        if (off < 64) {
            bool isq = off < 32;
            int k = off & 31;
            float sc = isq ? ATT_SCALE : 1.0f;
            unsigned short* Hd = (unsigned short*)(isq ? g_Qh : g_Kh);
            unsigned short* Ld = (unsigned short*)(isq ? g_Ql : g_Kl);
            size_t base = ((size_t)(b*HEADS + h) * NPIX + n0 + tn*4) * KD + k;
#pragma unroll
            for (int j = 0; j < 4; j++) {
                unsigned short hh, ll;
                bsplit(vals[j] * sc, hh, ll);
                Hd[base + (size_t)j*KD] = hh;
                Ld[base + (size_t)j*KD] = ll;
            }
        } else {
            size_t row = (size_t)(b*DIMC + h*HD + (off-64)) * NPIX + n0 + tn*4;
            *(float4*)&g_V[row] = make_float4(vals[0], vals[1], vals[2], vals[3]);
            *(uint2*)&g_Vh[row] = make_uint2(packbf(vals[0], vals[1]),
                                             packbf(vals[2], vals[3]));
        }
    }
}

// =============================================================================
// Kernel 2: flash attention via mma.sync, S split-bf16 3-pass, P/V bf16.
//   cp.async double-buffered K/V stages; 96.3 KB smem (2 CTAs/SM still fit).
// smem: Qh/Ql [128][32]@80B; per stage: Kh,Kl [128][32]@80B + Vh [64][128]@272B
// =============================================================================
#define AQH_O 0
#define AQL_O 10240
#define STG_O 20480
#define SKH 0
#define SKL 10240
#define SVH 20480
#define STG_SZ 37888
#define ATT_SMEM_BYTES (STG_O + 2*STG_SZ)   // 96256
#define NJ 32

__global__ __launch_bounds__(256) void attn_kernel()
{
    extern __shared__ char smb[];
    const int tid  = threadIdx.x;
    const int wid  = tid >> 5;
    const int lane = tid & 31;
    const int ib = blockIdx.x, h = blockIdx.y, b = blockIdx.z;
    const int i0 = ib * 128;
    const size_t bh = (size_t)(b*HEADS + h);

    const __nv_bfloat16* Qhg = g_Qh + bh * NPIX * KD;
    const __nv_bfloat16* Qlg = g_Ql + bh * NPIX * KD;
    const __nv_bfloat16* Khg = g_Kh + bh * NPIX * KD;
    const __nv_bfloat16* Klg = g_Kl + bh * NPIX * KD;
    const __nv_bfloat16* Vhg = g_Vh + (size_t)(b*DIMC + h*HD) * NPIX;
    float* Yg = g_Y + (size_t)(b*DIMC + h*HD) * NPIX;

    const u32 sbase = smem_u32(smb);

    // ---- Q tile via cp.async (group 0) ----
#pragma unroll
    for (int t = tid; t < 512; t += 256) {
        int row = t >> 2, ch = t & 3;
        cpa16(sbase + AQH_O + row*80 + ch*16, Qhg + (size_t)(i0+row)*KD + ch*8);
        cpa16(sbase + AQL_O + row*80 + ch*16, Qlg + (size_t)(i0+row)*KD + ch*8);
    }
    asm volatile("cp.async.commit_group;" ::: "memory");

    // ---- prefetch stage 0 (jt = 0) ----
    {
        const u32 st = sbase + STG_O;
#pragma unroll
        for (int t = tid; t < 512; t += 256) {
            int row = t >> 2, ch = t & 3;
            cpa16(st + SKH + row*80 + ch*16, Khg + (size_t)row*KD + ch*8);
            cpa16(st + SKL + row*80 + ch*16, Klg + (size_t)row*KD + ch*8);
        }
#pragma unroll
        for (int t = tid; t < 1024; t += 256) {
            int row = t >> 4, ch = t & 15;
            cpa16(st + SVH + row*272 + ch*16, Vhg + (size_t)row*NPIX + ch*8);
        }
        asm volatile("cp.async.commit_group;" ::: "memory");
    }

    // ---- Q fragments (Q group done; stage group may remain pending) ----
    asm volatile("cp.async.wait_group 1;" ::: "memory");
    __syncthreads();
    const int i0w = wid * 16;
    const int qrow = i0w + (lane & 7) + ((lane >> 3) & 1) * 8;
    const u32 qcb  = ((lane >> 4) & 1) * 16;
    u32 qh[2][4], ql[2][4];
#pragma unroll
    for (int ks = 0; ks < 2; ks++) {
        LDSM_X4(qh[ks][0], qh[ks][1], qh[ks][2], qh[ks][3],
                sbase + AQH_O + qrow*80 + ks*32 + qcb);
        LDSM_X4(ql[ks][0], ql[ks][1], ql[ks][2], ql[ks][3],
                sbase + AQL_O + qrow*80 + ks*32 + qcb);
    }

    const u32 kfr = (lane & 7)*80  + (lane >> 3)*16;
    const u32 vfr = (lane & 7)*272 + (lane >> 3)*16;

    float o[8][4];
#pragma unroll
    for (int nd = 0; nd < 8; nd++)
#pragma unroll
        for (int e = 0; e < 4; e++) o[nd][e] = 0.f;
    float ls0 = 0.f, ls1 = 0.f;

    for (int jt = 0; jt < NJ; jt++) {
        asm volatile("cp.async.wait_group 0;" ::: "memory");
        __syncthreads();

        // prefetch jt+1 into the other stage (all threads are past compute(jt-1))
        if (jt + 1 < NJ) {
            const u32 st = sbase + STG_O + ((jt+1) & 1)*STG_SZ;
            const int j0n = (jt+1) * 128;
#pragma unroll
            for (int t = tid; t < 512; t += 256) {
                int row = t >> 2, ch = t & 3;
                cpa16(st + SKH + row*80 + ch*16, Khg + (size_t)(j0n+row)*KD + ch*8);
                cpa16(st + SKL + row*80 + ch*16, Klg + (size_t)(j0n+row)*KD + ch*8);
            }
#pragma unroll
            for (int t = tid; t < 1024; t += 256) {
                int row = t >> 4, ch = t & 15;
                cpa16(st + SVH + row*272 + ch*16, Vhg + (size_t)row*NPIX + j0n + ch*8);
            }
        }
        asm volatile("cp.async.commit_group;" ::: "memory");

        const u32 st = sbase + STG_O + (jt & 1)*STG_SZ;

#pragma unroll
        for (int half = 0; half < 2; half++) {
            // ---- S = Q^T K over this 64-j half: 3-pass split ----
            float sd[8][4];
#pragma unroll
            for (int jn = 0; jn < 8; jn++)
#pragma unroll
                for (int e = 0; e < 4; e++) sd[jn][e] = 0.f;

            const u32 kh_b = st + SKH + half*5120 + kfr;
            const u32 kl_b = st + SKL + half*5120 + kfr;
#pragma unroll
            for (int jn = 0; jn < 8; jn++) {
                u32 k0,k1,k2,k3, l0,l1,l2,l3;
                LDSM_X4(k0,k1,k2,k3, kh_b + jn*640);
                LDSM_X4(l0,l1,l2,l3, kl_b + jn*640);
                mma16816(sd[jn], qh[0], k0, k1);
                mma16816(sd[jn], qh[1], k2, k3);
                mma16816(sd[jn], qh[0], l0, l1);
                mma16816(sd[jn], qh[1], l2, l3);
                mma16816(sd[jn], ql[0], k0, k1);
                mma16816(sd[jn], ql[1], k2, k3);
            }

            // ---- exp + row sums + P A-frags (bf16-rn) ----
            u32 ph[4][4];
#pragma unroll
            for (int jn = 0; jn < 8; jn++) {
                float p0 = __expf(sd[jn][0]);
                float p1 = __expf(sd[jn][1]);
                float p2 = __expf(sd[jn][2]);
                float p3 = __expf(sd[jn][3]);
                ls0 += p0 + p1;
                ls1 += p2 + p3;
                int af = jn >> 1, sel = (jn & 1) * 2;
                ph[af][sel+0] = packbf(p0, p1);
                ph[af][sel+1] = packbf(p2, p3);
            }

            // ---- O += P V^T over this half (V bf16) ----
            const u32 vh_b = st + SVH + half*128 + vfr;
#pragma unroll
            for (int p = 0; p < 2; p++) {
#pragma unroll
                for (int nd = 0; nd < 8; nd++) {
                    u32 a0,a1,a2,a3;
                    LDSM_X4(a0,a1,a2,a3, vh_b + nd*2176 + p*64);
                    mma16816(o[nd], ph[2*p],   a0, a1);
                    mma16816(o[nd], ph[2*p+1], a2, a3);
                }
            }
        }
    }

    // ---- row sums across the 4 lanes sharing each row ----
    ls0 += __shfl_xor_sync(0xFFFFFFFF, ls0, 1);
    ls0 += __shfl_xor_sync(0xFFFFFFFF, ls0, 2);
    ls1 += __shfl_xor_sync(0xFFFFFFFF, ls1, 1);
    ls1 += __shfl_xor_sync(0xFFFFFFFF, ls1, 2);
    float inv0 = 1.0f / ls0;
    float inv1 = 1.0f / ls1;

    // ---- store O ----
    const int iA = i0 + i0w + (lane >> 2);
    const int iB = iA + 8;
    const int dcol = (lane & 3) * 2;
#pragma unroll
    for (int nd = 0; nd < 8; nd++) {
        int d0 = nd*8 + dcol;
        Yg[(size_t)(d0  ) * NPIX + iA] = o[nd][0] * inv0;
        Yg[(size_t)(d0+1) * NPIX + iA] = o[nd][1] * inv0;
        Yg[(size_t)(d0  ) * NPIX + iB] = o[nd][2] * inv1;
        Yg[(size_t)(d0+1) * NPIX + iB] = o[nd][3] * inv1;
    }
}

// =============================================================================
// Kernel 3: Y += BN(depthwise 3x3 conv(V)), pad=1.
// =============================================================================
__global__ __launch_bounds__(256) void pe_kernel(
    const float* __restrict__ w, const float* __restrict__ gg,
    const float* __restrict__ bb, const float* __restrict__ mm,
    const float* __restrict__ vv)
{
    const int tid = threadIdx.x;
    const int xx = tid & 63;
    const int yy = blockIdx.x * 4 + (tid >> 6);
    const int c  = blockIdx.y;
    const int b  = blockIdx.z;

    const float* V = g_V + (size_t)(b*DIMC + c) * NPIX;
    float wgt[9];
#pragma unroll
    for (int t = 0; t < 9; t++) wgt[t] = w[c*9 + t];
    float s    = gg[c] * rsqrtf(vv[c] + EPS);
    float beta = bb[c] - mm[c] * s;

    float acc = 0.f;
#pragma unroll
    for (int dy = -1; dy <= 1; dy++) {
        int y2 = yy + dy;
        if (y2 < 0 || y2 > 63) continue;
#pragma unroll
        for (int dx = -1; dx <= 1; dx++) {
            int x2 = xx + dx;
            if (x2 < 0 || x2 > 63) continue;
            acc = fmaf(wgt[(dy+1)*3 + (dx+1)], V[y2*64 + x2], acc);
        }
    }
    g_Y[(size_t)(b*DIMC + c) * NPIX + yy*64 + xx] += fmaf(acc, s, beta);
}

// =============================================================================
// Kernel 4a: proj prep — split W*bn_scale into bf16 hi/lo, beta' per channel.
// =============================================================================
__global__ __launch_bounds__(256) void projprep_kernel(
    const float* __restrict__ w, const float* __restrict__ gg,
    const float* __restrict__ bb, const float* __restrict__ mm,
    const float* __restrict__ vv)
{
    int i = blockIdx.x * 256 + threadIdx.x;   // 65536
    int c = i >> 8, k = i & 255;
    float s = gg[c] * rsqrtf(vv[c] + EPS);
    unsigned short hh, ll;
    bsplit(w[i] * s, hh, ll);
    ((unsigned short*)g_Wph)[i] = hh;
    ((unsigned short*)g_Wpl)[i] = ll;
    if (k == 0) g_betap[c] = bb[c] - mm[c] * s;
}

// =============================================================================
// Kernel 4b: out = W'(bf16 split) @ Y + beta'.  mma.sync 3-pass.
//   CTA: 128 c x 128 n, 8 warps x 16 c.  8 k-tiles of 32.
// smem: Wh/Wl [128][32]@80B (10240 each), Yh/Yl [32][128]@272B (8704 each).
// =============================================================================
#define PJ_WH 0
#define PJ_WL 10240
#define PJ_YH 20480
#define PJ_YL 29184
#define PJ_SMEM 37888

__global__ __launch_bounds__(256) void proj_mma_kernel(float* __restrict__ out)
{
    __shared__ char smb[PJ_SMEM];
    const int tid  = threadIdx.x;
    const int wid  = tid >> 5;
    const int lane = tid & 31;
    const int n0 = blockIdx.x * 128;
    const int c0 = blockIdx.y * 128;
    const int b  = blockIdx.z;

    const float* yb = g_Y + (size_t)b * DIMC * NPIX;
    const u32 sbase = smem_u32(smb);

    float o[16][4];
#pragma unroll
    for (int nf = 0; nf < 16; nf++)
#pragma unroll
        for (int e = 0; e < 4; e++) o[nf][e] = 0.f;

    const int arow = wid*16 + (lane & 7) + ((lane >> 3) & 1) * 8;
    const u32 acb  = ((lane >> 4) & 1) * 16;
    const u32 bfr  = (lane & 15)*272 + (lane >> 4)*16;

    for (int kt = 0; kt < 8; kt++) {
        const int k0 = kt * 32;
        __syncthreads();
        // W tiles (pre-split bf16, uint4 copies)
#pragma unroll
        for (int t = tid; t < 512; t += 256) {
            int row = t >> 2, ch = t & 3;
            *(uint4*)(smb + PJ_WH + row*80 + ch*16) =
                *(const uint4*)&g_Wph[(c0 + row)*DIMC + k0 + ch*8];
            *(uint4*)(smb + PJ_WL + row*80 + ch*16) =
                *(const uint4*)&g_Wpl[(c0 + row)*DIMC + k0 + ch*8];
        }
        // Y tile [32 k][128 n] fp32 -> split bf16 hi/lo
#pragma unroll
        for (int t = tid; t < 1024; t += 256) {
            int kr = t >> 5, ch = t & 31;
            float4 v = *(const float4*)&yb[(size_t)(k0 + kr)*NPIX + n0 + ch*4];
            float h0 = bhi(v.x), h1 = bhi(v.y), h2 = bhi(v.z), h3 = bhi(v.w);
            *(uint2*)(smb + PJ_YH + kr*272 + ch*8) =
                make_uint2(packbf(h0, h1), packbf(h2, h3));
            *(uint2*)(smb + PJ_YL + kr*272 + ch*8) =
                make_uint2(packbf(v.x - h0, v.y - h1), packbf(v.z - h2, v.w - h3));
        }
        __syncthreads();

        // A fragments (2 k-steps, hi/lo)
        u32 awh[2][4], awl[2][4];
#pragma unroll
        for (int ks = 0; ks < 2; ks++) {
            LDSM_X4(awh[ks][0], awh[ks][1], awh[ks][2], awh[ks][3],
                    sbase + PJ_WH + arow*80 + ks*32 + acb);
            LDSM_X4(awl[ks][0], awl[ks][1], awl[ks][2], awl[ks][3],
                    sbase + PJ_WL + arow*80 + ks*32 + acb);
        }

        // B (trans from [k][n]) + mma, 3 passes
#pragma unroll
        for (int nf2 = 0; nf2 < 8; nf2++) {
#pragma unroll
            for (int ks = 0; ks < 2; ks++) {
                u32 h0,h1,h2,h3, l0,l1,l2,l3;
                LDSM_X4T(h0,h1,h2,h3, sbase + PJ_YH + bfr + ks*4352 + nf2*32);
                LDSM_X4T(l0,l1,l2,l3, sbase + PJ_YL + bfr + ks*4352 + nf2*32);
                mma16816(o[nf2*2  ], awh[ks], h0, h1);
                mma16816(o[nf2*2+1], awh[ks], h2, h3);
                mma16816(o[nf2*2  ], awh[ks], l0, l1);
                mma16816(o[nf2*2+1], awh[ks], l2, l3);
                mma16816(o[nf2*2  ], awl[ks], h0, h1);
                mma16816(o[nf2*2+1], awl[ks], h2, h3);
            }
        }
    }

    // epilogue: add beta, store
    const int cA = c0 + wid*16 + (lane >> 2);
    const int cB = cA + 8;
    const float betaA = g_betap[cA];
    const float betaB = g_betap[cB];
    float* outA = out + (size_t)(b*DIMC + cA) * NPIX + n0 + (lane & 3)*2;
    float* outB = out + (size_t)(b*DIMC + cB) * NPIX + n0 + (lane & 3)*2;
#pragma unroll
    for (int nf = 0; nf < 16; nf++) {
        *(float2*)&outA[nf*8] = make_float2(o[nf][0] + betaA, o[nf][1] + betaA);
        *(float2*)&outB[nf*8] = make_float2(o[nf][2] + betaB, o[nf][3] + betaB);
    }
}

// =============================================================================
extern "C" void kernel_launch(void* const* d_in, const int* in_sizes, int n_in,
                              void* d_out, int out_size)
{
    const float* x      = (const float*)d_in[0];
    const float* qkv_w  = (const float*)d_in[1];
    const float* qkv_g  = (const float*)d_in[2];
    const float* qkv_b  = (const float*)d_in[3];
    const float* qkv_m  = (const float*)d_in[4];
    const float* qkv_v  = (const float*)d_in[5];
    const float* proj_w = (const float*)d_in[6];
    const float* proj_g = (const float*)d_in[7];
    const float* proj_b = (const float*)d_in[8];
    const float* proj_m = (const float*)d_in[9];
    const float* proj_v = (const float*)d_in[10];
    const float* pe_w   = (const float*)d_in[11];
    const float* pe_g   = (const float*)d_in[12];
    const float* pe_b   = (const float*)d_in[13];
    const float* pe_m   = (const float*)d_in[14];
    const float* pe_v   = (const float*)d_in[15];
    float* out = (float*)d_out;

    cudaFuncSetAttribute(attn_kernel, cudaFuncAttributeMaxDynamicSharedMemorySize,
                         ATT_SMEM_BYTES);

    projprep_kernel<<<DIMC, 256>>>(proj_w, proj_g, proj_b, proj_m, proj_v);

    qkv_kernel<<<dim3(NPIX/64, HIDDEN/64, BATCH), 256>>>(
        x, qkv_w, qkv_g, qkv_b, qkv_m, qkv_v);

    attn_kernel<<<dim3(NPIX/128, HEADS, BATCH), 256, ATT_SMEM_BYTES>>>();

    pe_kernel<<<dim3(16, DIMC, BATCH), 256>>>(pe_w, pe_g, pe_b, pe_m, pe_v);

    proj_mma_kernel<<<dim3(NPIX/128, DIMC/128, BATCH), 256>>>(out);
}